// round 17
// baseline (speedup 1.0000x reference)
#include <cuda_runtime.h>
#include <cuda_fp16.h>
#include <math_constants.h>

// Problem constants (shapes fixed by the reference)
constexpr int NCH   = 32;     // n channels
constexpr int KNB   = 32;     // K neighbours
constexpr int MCL   = 16;     // M clusters
constexpr float MU_C = 1.0f;
constexpr int NMAX  = 131072; // scratch upper bound for N
constexpr int PB_BLOCKS = 296;   // kPB part: 2 blocks/SM
constexpr int KT_BLOCKS = 196;   // kT part: ceil(100000/512)

typedef unsigned long long ull;

// packed f32x2 helpers (sm_103a; rn per half == scalar fmaf bitwise)
__device__ __forceinline__ ull pk2(float lo, float hi) {
    ull r; asm("mov.b64 %0, {%1, %2};" : "=l"(r) : "f"(lo), "f"(hi)); return r;
}
__device__ __forceinline__ float2 upk2(ull v) {
    float2 r; asm("mov.b64 {%0, %1}, %2;" : "=f"(r.x), "=f"(r.y) : "l"(v)); return r;
}
__device__ __forceinline__ ull fma2p(ull a, ull b, ull c) {
    ull r; asm("fma.rn.f32x2 %0, %1, %2, %3;" : "=l"(r) : "l"(a), "l"(b), "l"(c)); return r;
}
__device__ __forceinline__ ull mul2p(ull a, ull b) {
    ull r; asm("mul.rn.f32x2 %0, %1, %2;" : "=l"(r) : "l"(a), "l"(b)); return r;
}

// ---- device scratch (no allocations allowed) ----
static __device__ float   g_encpart[16 * NCH];            // per-chunk partial dots for encoded
static __device__ float   g_encoded[NCH];                 // encoded vector
static __device__ float   g_a[MCL * NCH];                 // a[m][i] = 1/(bw[i,m]*MU)^2
static __device__ __half2 g_dect2[(size_t)NMAX * (NCH/2)];// dec_t[p][i] = half(decoder[i][p]*encoded[i])
static __device__ float   g_S[KNB * NCH];                 // S[k][i], atomically accumulated

// ------------------------------------------------------------------
// Kernel A: partial dot products for encoded[i] = enc_w[i,:] . x
// ------------------------------------------------------------------
__global__ void kA_encoded(const float* __restrict__ enc_w,
                           const float* __restrict__ x, int N) {
    int c = blockIdx.x;   // chunk
    int r = blockIdx.y;   // row (channel)
    int chunk = 4 * ((N + 63) / 64);      // 16 chunks of 4-aligned size
    int p0 = c * chunk;
    int p1 = min(p0 + chunk, N);

    const float* __restrict__ row = enc_w + (size_t)r * N;
    float s = 0.0f;
    int nv4 = (p1 - p0) / 4;              // p0 is 4-aligned
    const float4* __restrict__ row4 = reinterpret_cast<const float4*>(row + p0);
    const float4* __restrict__ x4   = reinterpret_cast<const float4*>(x + p0);
    for (int q = threadIdx.x; q < nv4; q += blockDim.x) {
        float4 a = row4[q], b = x4[q];
        s += a.x * b.x + a.y * b.y + a.z * b.z + a.w * b.w;
    }
    for (int p = p0 + 4 * nv4 + threadIdx.x; p < p1; p += blockDim.x)
        s += row[p] * x[p];

    #pragma unroll
    for (int o = 16; o > 0; o >>= 1)
        s += __shfl_xor_sync(0xffffffffu, s, o);

    __shared__ float ws[8];
    int lane = threadIdx.x & 31, wid = threadIdx.x >> 5;
    if (lane == 0) ws[wid] = s;
    __syncthreads();
    if (threadIdx.x == 0) {
        float t = 0.0f;
        #pragma unroll
        for (int w = 0; w < 8; w++) t += ws[w];
        g_encpart[c * NCH + r] = t;
    }
}

// ------------------------------------------------------------------
// Kernel B: reduce encoded partials, compute bandwidths -> a[m][i].
// Also zeroes g_S for this replay (runs before the fused kTB kernel).
// ------------------------------------------------------------------
__global__ void kB_bandwidths(const float* __restrict__ bw_w,
                              const float* __restrict__ bw_b,
                              const float* __restrict__ enc_b) {
    __shared__ float enc_s[NCH];
    int t = threadIdx.x;
    // zero the S accumulator (1024 floats, 512 threads)
    g_S[t] = 0.0f;
    g_S[t + 512] = 0.0f;

    if (t < NCH) {
        float s = enc_b[t];
        #pragma unroll
        for (int c = 0; c < 16; c++) s += g_encpart[c * NCH + t];
        enc_s[t] = s;
        g_encoded[t] = s;
    }
    __syncthreads();

    float s = bw_b[t];
    const float* __restrict__ wrow = bw_w + (size_t)t * NCH;
    #pragma unroll
    for (int q = 0; q < NCH; q++) s += wrow[q] * enc_s[q];
    float w = s * MU_C;
    int i = t / MCL, m = t % MCL;
    g_a[m * NCH + i] = 1.0f / (w * w);
}

// ------------------------------------------------------------------
// Fused kernel TB: blocks [0, KT_BLOCKS) run the decoder transpose,
// blocks [KT_BLOCKS, KT_BLOCKS+PB_BLOCKS) run the window-sum pass.
// Both depend only on kB outputs -> they run CONCURRENTLY.
// ------------------------------------------------------------------
__global__ void __launch_bounds__(512, 2) kTB_fused(
        const float* __restrict__ decoder,
        const float* __restrict__ nd, const int* __restrict__ labels, int N) {
    int t = threadIdx.x;

    if (blockIdx.x < KT_BLOCKS) {
        // ================= kT: transposed + encoded-folded decoder =========
        __shared__ float enc_s[NCH];
        if (t < NCH) enc_s[t] = g_encoded[t];
        __syncthreads();

        int p = blockIdx.x * 512 + t;
        if (p >= N) return;

        __half2 h[NCH / 2];
        #pragma unroll
        for (int q = 0; q < NCH / 2; q++) {
            float v0 = decoder[(size_t)(2 * q)     * N + p] * enc_s[2 * q];
            float v1 = decoder[(size_t)(2 * q + 1) * N + p] * enc_s[2 * q + 1];
            h[q] = __floats2half2_rn(v0, v1);
        }
        uint4* dst = reinterpret_cast<uint4*>(g_dect2 + (size_t)p * (NCH / 2));
        const uint4* src = reinterpret_cast<const uint4*>(h);
        #pragma unroll
        for (int q = 0; q < 4; q++) dst[q] = src[q];
        return;
    }

    // ================= kPB: S[i,k] = sum_j relu(1 - d^2 * a) =============
    int pbid = blockIdx.x - KT_BLOCKS;      // 0..PB_BLOCKS-1

    __shared__ float a_s[MCL * NCH];
    __shared__ float S_sm[KNB * NCH];
    __shared__ __align__(16) float d2w[16][4][KNB];   // [warp][jj][k] = -d^2
    if (t < MCL * NCH) a_s[t] = g_a[t];
    for (int u = t; u < KNB * NCH; u += 512) S_sm[u] = 0.0f;
    __syncthreads();

    int lane = t & 31, wid = t >> 5;       // 16 warps
    int gw = pbid * 16 + wid;
    int nwj = PB_BLOCKS * 16 * 4;          // j stride (4 j per warp per stage)

    ull one2 = pk2(1.0f, 1.0f);

    float acc[KNB];
    #pragma unroll
    for (int k = 0; k < KNB; k++) acc[k] = 0.0f;

    for (int jb = gw * 4; jb < N; jb += nwj) {
        float nd2v[4];
        int   labv[4];
        #pragma unroll
        for (int u = 0; u < 4; u++) {
            int j = jb + u;
            bool ok = (j < N);
            float dd = ok ? nd[(size_t)j * KNB + lane] : 0.0f;
            nd2v[u] = ok ? (-dd * dd) : -CUDART_INF_F;
            labv[u] = ok ? labels[j] : 0;
        }
        __syncwarp();                       // WAR: prior reads done
        #pragma unroll
        for (int u = 0; u < 4; u++) d2w[wid][u][lane] = nd2v[u];
        __syncwarp();                       // RAW: stores visible

        #pragma unroll
        for (int u = 0; u < 4; u++) {
            float a = a_s[labv[u] * NCH + lane];   // lane = channel i
            ull a2 = pk2(a, a);
            unsigned sbase = (unsigned)__cvta_generic_to_shared(&d2w[wid][u][0]);
            #pragma unroll
            for (int kq = 0; kq < KNB / 4; kq++) {
                ull q0, q1;
                asm volatile("ld.shared.v2.u64 {%0, %1}, [%2];"
                             : "=l"(q0), "=l"(q1) : "r"(sbase + 16u * kq));
                ull w0 = fma2p(q0, a2, one2);
                ull w1 = fma2p(q1, a2, one2);
                float2 f01 = upk2(w0), f23 = upk2(w1);
                acc[4 * kq + 0] += fmaxf(f01.x, 0.0f);
                acc[4 * kq + 1] += fmaxf(f01.y, 0.0f);
                acc[4 * kq + 2] += fmaxf(f23.x, 0.0f);
                acc[4 * kq + 3] += fmaxf(f23.y, 0.0f);
            }
        }
    }

    #pragma unroll
    for (int k = 0; k < KNB; k++)
        atomicAdd(&S_sm[k * NCH + lane], acc[k]);
    __syncthreads();

    // spread-address global accumulation (REDG, no return)
    for (int u = t; u < KNB * NCH; u += 512)
        atomicAdd(&g_S[u], S_sm[u]);
}

// ------------------------------------------------------------------
// Kernel PC v9: out[j] = sum_{k,i} dec_t*win*invS — PACKED f32x2 math.
// warp = 4 points (8 lanes each), lane = channel QUAD, LDG.64 gathers,
// 2-slot gather ring. Staged value is -d^2 (negation folded into FMUL).
// Window: fma.rn.f32x2; clamp: scalar FMNMX on aliased halves;
// product+acc: mul.rn.f32x2 + fma.rn.f32x2. Bitwise == scalar version.
// ------------------------------------------------------------------
__global__ void __launch_bounds__(512, 2) kPC_output(
        const float4* __restrict__ nd4, const int4* __restrict__ nid4,
        const int* __restrict__ labels, float* __restrict__ out, int N) {
    __shared__ __align__(16) float a_s[MCL][NCH];      // [lab][ch]
    __shared__ __align__(16) float ivs_s[KNB][8][4];   // [k][chquad][4]
    __shared__ __align__(16) float d2_sm[16][4][KNB];  // [wid][jj][k] = -d^2
    __shared__ __align__(16) int   id_sm[16][4][KNB];  // [wid][jj][k]

    int t = threadIdx.x;
    for (int u = t; u < MCL * NCH; u += 512)
        a_s[u / NCH][u % NCH] = g_a[u];
    for (int u = t; u < KNB * NCH; u += 512) {
        int k = u / NCH, i = u % NCH;
        ivs_s[k][i >> 2][i & 3] = 1.0f / g_S[u];
    }
    __syncthreads();

    int lane = t & 31, wid = t >> 5;     // 16 warps
    int jj   = lane >> 3;                // which of 4 points
    int sub  = lane & 7;                 // channel quad (channels 4sub..4sub+3)

    const uint2* __restrict__ gb = reinterpret_cast<const uint2*>(g_dect2) + sub;

    ull one2 = pk2(1.0f, 1.0f);

    int P  = (N + 3) >> 2;               // number of j-quads
    int nw = gridDim.x * 16;

    for (int p = blockIdx.x * 16 + wid; p < P; p += nw) {
        int j  = 4 * p + jj;
        int jm = min(j, N - 1);

        // coalesced row loads: 8 lanes x float4/int4 = 128B per point
        float4 dp = nd4[(unsigned)jm * 8u + sub];
        int4   ip = nid4[(unsigned)jm * 8u + sub];

        __syncwarp();
        // stage NEGATED d^2 (negation folded into the FMUL)
        *reinterpret_cast<float4*>(&d2_sm[wid][jj][4 * sub]) =
            make_float4(-dp.x * dp.x, -dp.y * dp.y, -dp.z * dp.z, -dp.w * dp.w);
        *reinterpret_cast<int4*>(&id_sm[wid][jj][4 * sub]) = ip;
        __syncwarp();

        int lab = labels[jm];
        float4 av = *reinterpret_cast<const float4*>(&a_s[lab][4 * sub]);
        ull a01 = pk2(av.x, av.y);
        ull a23 = pk2(av.z, av.w);

        // ---- prologue: issue gathers for k = 0..3 (kp = 0,1) ----
        uint2 vh[2][2];
        {
            int4 id03 = *reinterpret_cast<const int4*>(&id_sm[wid][jj][0]);
            vh[0][0] = gb[(unsigned)id03.x * 8u];
            vh[0][1] = gb[(unsigned)id03.y * 8u];
            vh[1][0] = gb[(unsigned)id03.z * 8u];
            vh[1][1] = gb[(unsigned)id03.w * 8u];
        }

        ull acc01 = pk2(0.0f, 0.0f);
        ull acc23 = pk2(0.0f, 0.0f);
        #pragma unroll
        for (int kp = 0; kp < 16; kp++) {
            uint2 u0 = vh[kp & 1][0];     // row for k = 2kp   (4 halves)
            uint2 u1 = vh[kp & 1][1];     // row for k = 2kp+1

            if (kp + 2 < 16) {            // re-issue freed slot for kp+2
                int2 idn = *reinterpret_cast<const int2*>(&id_sm[wid][jj][2 * (kp + 2)]);
                vh[kp & 1][0] = gb[(unsigned)idn.x * 8u];
                vh[kp & 1][1] = gb[(unsigned)idn.y * 8u];
            }

            float2 d2 = *reinterpret_cast<const float2*>(&d2_sm[wid][jj][2 * kp]); // -d^2
            ull dk0 = pk2(d2.x, d2.x);
            ull dk1 = pk2(d2.y, d2.y);
            ulonglong2 iv0 = *reinterpret_cast<const ulonglong2*>(&ivs_s[2 * kp][sub][0]);
            ulonglong2 iv1 = *reinterpret_cast<const ulonglong2*>(&ivs_s[2 * kp + 1][sub][0]);

            // k = 2kp
            {
                ull w01 = fma2p(dk0, a01, one2);
                ull w23 = fma2p(dk0, a23, one2);
                float2 f01 = upk2(w01), f23 = upk2(w23);
                ull wc01 = pk2(fmaxf(f01.x, 0.0f), fmaxf(f01.y, 0.0f));
                ull wc23 = pk2(fmaxf(f23.x, 0.0f), fmaxf(f23.y, 0.0f));
                float2 va = __half22float2(*reinterpret_cast<__half2*>(&u0.x));
                float2 vb = __half22float2(*reinterpret_cast<__half2*>(&u0.y));
                ull t01 = mul2p(pk2(va.x, va.y), wc01);
                ull t23 = mul2p(pk2(vb.x, vb.y), wc23);
                acc01 = fma2p(t01, iv0.x, acc01);
                acc23 = fma2p(t23, iv0.y, acc23);
            }
            // k = 2kp+1
            {
                ull w01 = fma2p(dk1, a01, one2);
                ull w23 = fma2p(dk1, a23, one2);
                float2 f01 = upk2(w01), f23 = upk2(w23);
                ull wc01 = pk2(fmaxf(f01.x, 0.0f), fmaxf(f01.y, 0.0f));
                ull wc23 = pk2(fmaxf(f23.x, 0.0f), fmaxf(f23.y, 0.0f));
                float2 va = __half22float2(*reinterpret_cast<__half2*>(&u1.x));
                float2 vb = __half22float2(*reinterpret_cast<__half2*>(&u1.y));
                ull t01 = mul2p(pk2(va.x, va.y), wc01);
                ull t23 = mul2p(pk2(vb.x, vb.y), wc23);
                acc01 = fma2p(t01, iv1.x, acc01);
                acc23 = fma2p(t23, iv1.y, acc23);
            }
        }

        float2 r01 = upk2(acc01), r23 = upk2(acc23);
        float s = (r01.x + r01.y) + (r23.x + r23.y);
        #pragma unroll
        for (int o = 1; o < 8; o <<= 1)
            s += __shfl_xor_sync(0xffffffffu, s, o);   // reduce over 8-lane group

        if (sub == 0 && j < N) out[j] = s;
    }
}

// ------------------------------------------------------------------
extern "C" void kernel_launch(void* const* d_in, const int* in_sizes, int n_in,
                              void* d_out, int out_size) {
    const float* x       = (const float*)d_in[0];
    const float* enc_w   = (const float*)d_in[1];
    const float* enc_b   = (const float*)d_in[2];
    const float* decoder = (const float*)d_in[3];
    const float* bw_w    = (const float*)d_in[4];
    const float* bw_b    = (const float*)d_in[5];
    const float* nd      = (const float*)d_in[6];
    const int*   nid     = (const int*)d_in[7];
    const int*   labels  = (const int*)d_in[8];
    float* out = (float*)d_out;
    int N = in_sizes[0];

    kA_encoded<<<dim3(16, NCH), 256>>>(enc_w, x, N);
    kB_bandwidths<<<1, NCH * MCL>>>(bw_w, bw_b, enc_b);
    kTB_fused<<<KT_BLOCKS + PB_BLOCKS, 512>>>(decoder, nd, labels, N);
    kPC_output<<<296, 512>>>((const float4*)nd, (const int4*)nid, labels, out, N);
}